// round 16
// baseline (speedup 1.0000x reference)
#include <cuda_runtime.h>
#include <cstdint>

#define BB     64
#define TOPK   2
#define EE     16
#define CC     1024
#define KK     4096
#define NTOK   128

#define MT     128             // c-rows per CTA
#define NT     16              // tokens per CTA chunk
#define KD     32              // k-floats per stage
#define JST    (KK / KD)       // 128 stages
#define NSLOT  8               // pow2 ring

#define ROWB   144             // padded smem row stride (bank-conflict-free)
#define W_OFF  0
#define A_OFF  (MT * ROWB)                  // 18432
#define STG_BYTES (MT * ROWB + NT * ROWB)   // 20736
#define DYN_BYTES (NSLOT * STG_BYTES)       // 165888

__device__ float g_tmp[NTOK * CC];

// ---- PTX helpers -----------------------------------------------------------
__device__ __forceinline__ void cp16(uint32_t dst, const void* src) {
    asm volatile("cp.async.cg.shared.global [%0], [%1], 16;"
                 :: "r"(dst), "l"(src) : "memory");
}
__device__ __forceinline__ void cp_commit() {
    asm volatile("cp.async.commit_group;" ::: "memory");
}
template <int N>
__device__ __forceinline__ void cp_wait() {
    asm volatile("cp.async.wait_group %0;" :: "n"(N) : "memory");
}
__device__ __forceinline__ float lds_f32(uint32_t a) {
    float v;
    asm volatile("ld.shared.f32 %0, [%1];" : "=f"(v) : "r"(a));
    return v;
}
// fp32 -> tf32 with round-to-nearest (RNA): halves error vs HW truncation
__device__ __forceinline__ uint32_t to_tf32(float v) {
    uint32_t r;
    asm("cvt.rna.tf32.f32 %0, %1;" : "=r"(r) : "f"(v));
    return r;
}
__device__ __forceinline__ void mma_tf32(float& d0, float& d1, float& d2, float& d3,
                                         uint32_t a0, uint32_t a1, uint32_t a2,
                                         uint32_t a3, uint32_t b0, uint32_t b1) {
    asm volatile(
        "mma.sync.aligned.m16n8k8.row.col.f32.tf32.tf32.f32 "
        "{%0,%1,%2,%3}, {%4,%5,%6,%7}, {%8,%9}, {%0,%1,%2,%3};"
        : "+f"(d0), "+f"(d1), "+f"(d2), "+f"(d3)
        : "r"(a0), "r"(a1), "r"(a2), "r"(a3), "r"(b0), "r"(b1));
}

// ---------------------------------------------------------------------------
// tf32 mma.sync grouped expert matvec.
// Grid (2, CC/MT=8, EE=16): x = token-chunk, y = c-tile, z = expert.
// Block 128 (4 warps), 1 CTA/SM (166KB smem ring), single wave (~136 CTAs).
// D[16 tok, 128 rows] accumulated in fp32 registers over 128 K-stages of 32.
// Stage smem: W [128 rows][144B] + A [16 tok][144B], cp.async-filled
// (9 cp16/thread/stage), 8-slot ring, 6 groups in flight.
// Consume (per warp, rows warp*32..+31): MMA M=token, K=k, N=row;
// fragments via conflict-free LDS.32 + cvt.rna.tf32.
// ---------------------------------------------------------------------------
__global__ void __launch_bounds__(128, 1)
matvec(const float* __restrict__ act,
       const float* __restrict__ W,
       const int*  __restrict__ eidx) {
    extern __shared__ float4 stf4[];
    __shared__ int se[NTOK];
    __shared__ int stok[NTOK];

    const int tid = threadIdx.x;
    const int e   = blockIdx.z;

    se[tid] = eidx[tid];                       // 128 threads == NTOK
    __syncthreads();
    int mine = (se[tid] == e);
    if (mine) {
        int pos = 0;
        for (int j = 0; j < tid; ++j) pos += (se[j] == e) ? 1 : 0;
        stok[pos] = tid;
    }
    const int cnt = __syncthreads_count(mine);

    const int chunkbase = blockIdx.x * NT;
    if (cnt == 0 || chunkbase >= cnt) return;  // uniform exit

    const int warp = tid >> 5;
    const int lane = tid & 31;
    const int c0   = blockIdx.y * MT;

    const uint32_t st0 = (uint32_t)__cvta_generic_to_shared(stf4);

    // W fill source: this thread's row of the 128-row tile
    const float* __restrict__ wrow = W + ((size_t)(e * CC + c0) + tid) * KK;
    const uint32_t wdst = st0 + W_OFF + (uint32_t)tid * ROWB;          // + c*16
    const uint32_t adst = st0 + A_OFF + (uint32_t)(tid >> 3) * ROWB
                              + (uint32_t)(tid & 7) * 16;

    // consume-side address components
    const uint32_t kq = (uint32_t)(lane & 3) * 4;          // k = l%4 (bytes)
    const uint32_t arow_off = A_OFF + (uint32_t)(lane >> 2) * ROWB;
    const uint32_t brow_off = W_OFF + (uint32_t)(warp * 32 + (lane >> 2)) * ROWB;

    for (int t0 = chunkbase; t0 < cnt; t0 += 2 * NT) {
        // A fill source: token t0 + tid/8 (clamped), 16B chunk tid%8
        int tt = t0 + (tid >> 3);
        if (tt >= cnt) tt = cnt - 1;
        const float* asrc = act + (size_t)stok[tt] * KK + (tid & 7) * 4;

        float d[4][4];
#pragma unroll
        for (int rt = 0; rt < 4; ++rt)
#pragma unroll
            for (int i = 0; i < 4; ++i) d[rt][i] = 0.0f;

        // ---- prime slots 0 .. NSLOT-2 ----
#pragma unroll
        for (int s = 0; s < NSLOT - 1; ++s) {
            const int k0 = s * KD;
            const uint32_t sb = (uint32_t)s * STG_BYTES;
#pragma unroll
            for (int c = 0; c < 8; ++c)
                cp16(wdst + sb + c * 16, wrow + k0 + c * 4);
            cp16(adst + sb, asrc + k0);
            cp_commit();
        }

#pragma unroll 1
        for (int j = 0; j < JST; ++j) {
            cp_wait<NSLOT - 2>();              // stage j arrived
            __syncthreads();                   // visible; j-1 consumed by all

            const int jf = j + NSLOT - 1;
            if (jf < JST) {
                const int k0 = jf * KD;
                const uint32_t sb = (uint32_t)(jf & (NSLOT - 1)) * STG_BYTES;
#pragma unroll
                for (int c = 0; c < 8; ++c)
                    cp16(wdst + sb + c * 16, wrow + k0 + c * 4);
                cp16(adst + sb, asrc + k0);
            }
            cp_commit();                       // every j: counts stay aligned

            // ---- consume slot j&7 ----
            const uint32_t sb = st0 + (uint32_t)(j & (NSLOT - 1)) * STG_BYTES;
            const uint32_t ar = sb + arow_off;
            const uint32_t br = sb + brow_off;

#pragma unroll
            for (int kt = 0; kt < 4; ++kt) {
                const uint32_t ka = kt * 32;   // 8 floats per k-tile
                // A fragment (M=token): a0 (m=l/4,k=l%4) a1 (m+8) a2 (k+4) a3
                uint32_t a0 = to_tf32(lds_f32(ar + ka + kq));
                uint32_t a1 = to_tf32(lds_f32(ar + 8 * ROWB + ka + kq));
                uint32_t a2 = to_tf32(lds_f32(ar + ka + kq + 16));
                uint32_t a3 = to_tf32(lds_f32(ar + 8 * ROWB + ka + kq + 16));
#pragma unroll
                for (int rt = 0; rt < 4; ++rt) {
                    // B fragment (N=row): b0 (k=l%4,n=l/4) b1 (k+4)
                    const uint32_t ba = br + (uint32_t)(rt * 8) * ROWB + ka + kq;
                    uint32_t b0 = to_tf32(lds_f32(ba));
                    uint32_t b1 = to_tf32(lds_f32(ba + 16));
                    mma_tf32(d[rt][0], d[rt][1], d[rt][2], d[rt][3],
                             a0, a1, a2, a3, b0, b1);
                }
            }
        }

        // ---- epilogue: D[m=token][n=row] register fragments -> g_tmp ----
        // d0: (m=l/4, n=2*(l%4)) d1: n+1  d2: (m+8, n) d3: (m+8, n+1)
        const int ta = t0 + (lane >> 2);
        const int tb = ta + 8;
#pragma unroll
        for (int rt = 0; rt < 4; ++rt) {
            const int row = c0 + warp * 32 + rt * 8 + 2 * (lane & 3);
            if (ta < cnt) {
                float2 v = make_float2(d[rt][0], d[rt][1]);
                *reinterpret_cast<float2*>(&g_tmp[stok[ta] * CC + row]) = v;
            }
            if (tb < cnt) {
                float2 v = make_float2(d[rt][2], d[rt][3]);
                *reinterpret_cast<float2*>(&g_tmp[stok[tb] * CC + row]) = v;
            }
        }
        __syncthreads();   // all stage reads done before next chunk re-primes
    }
}

// ---------------------------------------------------------------------------
// finalize: out = residual + sum_s ew * (tmp + bias[e])
// ---------------------------------------------------------------------------
__global__ void __launch_bounds__(128)
finalize(const float* __restrict__ residual,
         const float* __restrict__ bias,
         const float* __restrict__ ew,
         const int*  __restrict__ eidx,
         float* __restrict__ out) {
    const int idx = blockIdx.x * blockDim.x + threadIdx.x;   // over BB*CC/4
    const int b   = idx >> 8;                                // CC/4 = 256
    const int c4  = idx & 255;

    const float4* r4 = reinterpret_cast<const float4*>(residual);
    const float4* b4 = reinterpret_cast<const float4*>(bias);
    const float4* t4 = reinterpret_cast<const float4*>(g_tmp);
    float4 v = r4[(b << 8) + c4];
#pragma unroll
    for (int s = 0; s < TOPK; ++s) {
        const int   e = eidx[b * TOPK + s];
        const float w = ew[b * TOPK + s];
        float4 t  = t4[((b * TOPK + s) << 8) + c4];
        float4 bb = b4[(e << 8) + c4];
        v.x += w * (t.x + bb.x);
        v.y += w * (t.y + bb.y);
        v.z += w * (t.z + bb.z);
        v.w += w * (t.w + bb.w);
    }
    reinterpret_cast<float4*>(out)[(b << 8) + c4] = v;
}

// ---------------------------------------------------------------------------
extern "C" void kernel_launch(void* const* d_in, const int* in_sizes, int n_in,
                              void* d_out, int out_size) {
    const float* activated      = (const float*)d_in[0];
    const int*   expert_indices = (const int*)  d_in[1];
    const float* expert_weights = (const float*)d_in[2];
    const float* mlp2_weight    = (const float*)d_in[3];
    const float* mlp2_bias      = (const float*)d_in[4];
    const float* residual_x     = (const float*)d_in[5];
    float*       out            = (float*)d_out;

    static bool attr_done = false;
    if (!attr_done) {
        cudaFuncSetAttribute(matvec, cudaFuncAttributeMaxDynamicSharedMemorySize,
                             DYN_BYTES);
        attr_done = true;
    }

    dim3 grid(2, CC / MT, EE);   // chunk fastest; ~136 active CTAs, one wave
    matvec<<<grid, 128, DYN_BYTES>>>(activated, mlp2_weight, expert_indices);

    finalize<<<(BB * CC / 4) / 128, 128>>>(residual_x, mlp2_bias,
                                           expert_weights, expert_indices, out);
}

// round 17
// speedup vs baseline: 1.1498x; 1.1498x over previous
#include <cuda_runtime.h>
#include <cstdint>

#define BB     64
#define TOPK   2
#define EE     16
#define CC     1024
#define KK     4096
#define NTOK   128

#define MT     128             // c-rows per CTA
#define NT     16              // tokens per CTA chunk (MMA M)
#define KD     32              // k-floats per stage
#define JST    (KK / KD)       // 128 stages
#define NSLOT  8               // pow2 ring

#define THREADS 256            // 8 warps -> 2 per SMSP
#define RPWARP  16             // rows per warp (2 x N=8 tiles)

#define ROWB   144             // padded smem row stride (bank-conflict-free)
#define W_OFF  0
#define A_OFF  (MT * ROWB)                  // 18432
#define STG_BYTES (MT * ROWB + NT * ROWB)   // 20736
#define DYN_BYTES (NSLOT * STG_BYTES)       // 165888

__device__ float g_tmp[NTOK * CC];

// ---- PTX helpers -----------------------------------------------------------
__device__ __forceinline__ void cp16(uint32_t dst, const void* src) {
    asm volatile("cp.async.cg.shared.global [%0], [%1], 16;"
                 :: "r"(dst), "l"(src) : "memory");
}
__device__ __forceinline__ void cp_commit() {
    asm volatile("cp.async.commit_group;" ::: "memory");
}
template <int N>
__device__ __forceinline__ void cp_wait() {
    asm volatile("cp.async.wait_group %0;" :: "n"(N) : "memory");
}
__device__ __forceinline__ float lds_f32(uint32_t a) {
    float v;
    asm volatile("ld.shared.f32 %0, [%1];" : "=f"(v) : "r"(a));
    return v;
}
// fp32 -> tf32 round-to-nearest (RNA): halves error vs HW truncation
__device__ __forceinline__ uint32_t to_tf32(float v) {
    uint32_t r;
    asm("cvt.rna.tf32.f32 %0, %1;" : "=r"(r) : "f"(v));
    return r;
}
__device__ __forceinline__ void mma_tf32(float& d0, float& d1, float& d2, float& d3,
                                         uint32_t a0, uint32_t a1, uint32_t a2,
                                         uint32_t a3, uint32_t b0, uint32_t b1) {
    asm volatile(
        "mma.sync.aligned.m16n8k8.row.col.f32.tf32.tf32.f32 "
        "{%0,%1,%2,%3}, {%4,%5,%6,%7}, {%8,%9}, {%0,%1,%2,%3};"
        : "+f"(d0), "+f"(d1), "+f"(d2), "+f"(d3)
        : "r"(a0), "r"(a1), "r"(a2), "r"(a3), "r"(b0), "r"(b1));
}

// ---------------------------------------------------------------------------
// tf32 mma.sync grouped expert matvec — 8-warp CTA (2 warps/SMSP).
// Grid (2, CC/MT=8, EE=16): x = token-chunk, y = c-tile, z = expert.
// Block 256, 1 CTA/SM (166KB ring), single wave (~136 active CTAs).
// D[16 tok, 128 rows]: warp owns 16 rows; 8 mma per k-step per warp.
// Stage smem: W [128 rows][144B] + A [16 tok][144B]; fill: 4 W-cp16/thread
// (+1 A-cp16 for threads<128); 8-slot ring, 6 groups in flight.
// fp32 register accumulation over all 128 k-steps (deterministic).
// ---------------------------------------------------------------------------
__global__ void __launch_bounds__(THREADS, 1)
matvec(const float* __restrict__ act,
       const float* __restrict__ W,
       const int*  __restrict__ eidx) {
    extern __shared__ float4 stf4[];
    __shared__ int se[NTOK];
    __shared__ int stok[NTOK];

    const int tid = threadIdx.x;
    const int e   = blockIdx.z;

    if (tid < NTOK) se[tid] = eidx[tid];
    __syncthreads();
    int mine = (tid < NTOK) && (se[tid] == e);
    if (mine) {
        int pos = 0;
        for (int j = 0; j < tid; ++j) pos += (se[j] == e) ? 1 : 0;
        stok[pos] = tid;
    }
    const int cnt = __syncthreads_count(mine);

    const int chunkbase = blockIdx.x * NT;
    if (cnt == 0 || chunkbase >= cnt) return;  // uniform exit

    const int warp = tid >> 5;
    const int lane = tid & 31;
    const int c0   = blockIdx.y * MT;

    const uint32_t st0 = (uint32_t)__cvta_generic_to_shared(stf4);

    // W fill: thread stages row tid/2, 64B half (tid&1): 4 cp16
    const int   wr   = tid >> 1;
    const float* __restrict__ wrow =
        W + ((size_t)(e * CC + c0) + wr) * KK + (tid & 1) * 16;
    const uint32_t wdst = st0 + W_OFF + (uint32_t)wr * ROWB + (tid & 1) * 64;
    // A fill (threads < 128): token tid/8, 16B chunk tid%8
    const uint32_t adst = st0 + A_OFF + (uint32_t)(tid >> 3) * ROWB
                              + (uint32_t)(tid & 7) * 16;

    // consume-side address components
    const uint32_t kq       = (uint32_t)(lane & 3) * 4;        // k byte offset
    const uint32_t arow_off = A_OFF + (uint32_t)(lane >> 2) * ROWB;
    const uint32_t brow_off = W_OFF + (uint32_t)(warp * RPWARP + (lane >> 2)) * ROWB;

    for (int t0 = chunkbase; t0 < cnt; t0 += 2 * NT) {
        const float* asrc = nullptr;
        if (tid < 128) {
            int tt = t0 + (tid >> 3);
            if (tt >= cnt) tt = cnt - 1;
            asrc = act + (size_t)stok[tt] * KK + (tid & 7) * 4;
        }

        float d[2][4];
#pragma unroll
        for (int rt = 0; rt < 2; ++rt)
#pragma unroll
            for (int i = 0; i < 4; ++i) d[rt][i] = 0.0f;

        // ---- prime slots 0 .. NSLOT-2 ----
#pragma unroll
        for (int s = 0; s < NSLOT - 1; ++s) {
            const int k0 = s * KD;
            const uint32_t sb = (uint32_t)s * STG_BYTES;
#pragma unroll
            for (int c = 0; c < 4; ++c)
                cp16(wdst + sb + c * 16, wrow + k0 + c * 4);
            if (tid < 128) cp16(adst + sb, asrc + k0);
            cp_commit();
        }

#pragma unroll 1
        for (int j = 0; j < JST; ++j) {
            cp_wait<NSLOT - 2>();              // stage j arrived
            __syncthreads();                   // visible; j-1 consumed by all

            const int jf = j + NSLOT - 1;
            if (jf < JST) {
                const int k0 = jf * KD;
                const uint32_t sb = (uint32_t)(jf & (NSLOT - 1)) * STG_BYTES;
#pragma unroll
                for (int c = 0; c < 4; ++c)
                    cp16(wdst + sb + c * 16, wrow + k0 + c * 4);
                if (tid < 128) cp16(adst + sb, asrc + k0);
            }
            cp_commit();                       // every j: counts stay aligned

            // ---- consume slot j&7 ----
            const uint32_t sb = st0 + (uint32_t)(j & (NSLOT - 1)) * STG_BYTES;
            const uint32_t ar = sb + arow_off;
            const uint32_t br = sb + brow_off;

#pragma unroll
            for (int kt = 0; kt < 4; ++kt) {
                const uint32_t ka = kt * 32;   // 8 floats per k-tile
                // A fragment (M=token): a0 (m=l/4,k=l%4) a1 (m+8) a2 (k+4) a3
                uint32_t a0 = to_tf32(lds_f32(ar + ka + kq));
                uint32_t a1 = to_tf32(lds_f32(ar + 8 * ROWB + ka + kq));
                uint32_t a2 = to_tf32(lds_f32(ar + ka + kq + 16));
                uint32_t a3 = to_tf32(lds_f32(ar + 8 * ROWB + ka + kq + 16));
#pragma unroll
                for (int rt = 0; rt < 2; ++rt) {
                    // B fragment (N=row): b0 (k=l%4,n=l/4) b1 (k+4)
                    const uint32_t ba = br + (uint32_t)(rt * 8) * ROWB + ka + kq;
                    uint32_t b0 = to_tf32(lds_f32(ba));
                    uint32_t b1 = to_tf32(lds_f32(ba + 16));
                    mma_tf32(d[rt][0], d[rt][1], d[rt][2], d[rt][3],
                             a0, a1, a2, a3, b0, b1);
                }
            }
        }

        // ---- epilogue: D[m=token][n=row] -> g_tmp ----
        // d0 (m=l/4, n=2*(l%4)) d1 n+1  d2 (m+8, n) d3 (m+8, n+1)
        const int ta = t0 + (lane >> 2);
        const int tb = ta + 8;
#pragma unroll
        for (int rt = 0; rt < 2; ++rt) {
            const int row = c0 + warp * RPWARP + rt * 8 + 2 * (lane & 3);
            if (ta < cnt) {
                float2 v = make_float2(d[rt][0], d[rt][1]);
                *reinterpret_cast<float2*>(&g_tmp[stok[ta] * CC + row]) = v;
            }
            if (tb < cnt) {
                float2 v = make_float2(d[rt][2], d[rt][3]);
                *reinterpret_cast<float2*>(&g_tmp[stok[tb] * CC + row]) = v;
            }
        }
        __syncthreads();   // all stage reads done before next chunk re-primes
    }
}

// ---------------------------------------------------------------------------
// finalize: out = residual + sum_s ew * (tmp + bias[e])
// ---------------------------------------------------------------------------
__global__ void __launch_bounds__(128)
finalize(const float* __restrict__ residual,
         const float* __restrict__ bias,
         const float* __restrict__ ew,
         const int*  __restrict__ eidx,
         float* __restrict__ out) {
    const int idx = blockIdx.x * blockDim.x + threadIdx.x;   // over BB*CC/4
    const int b   = idx >> 8;                                // CC/4 = 256
    const int c4  = idx & 255;

    const float4* r4 = reinterpret_cast<const float4*>(residual);
    const float4* b4 = reinterpret_cast<const float4*>(bias);
    const float4* t4 = reinterpret_cast<const float4*>(g_tmp);
    float4 v = r4[(b << 8) + c4];
#pragma unroll
    for (int s = 0; s < TOPK; ++s) {
        const int   e = eidx[b * TOPK + s];
        const float w = ew[b * TOPK + s];
        float4 t  = t4[((b * TOPK + s) << 8) + c4];
        float4 bb = b4[(e << 8) + c4];
        v.x += w * (t.x + bb.x);
        v.y += w * (t.y + bb.y);
        v.z += w * (t.z + bb.z);
        v.w += w * (t.w + bb.w);
    }
    reinterpret_cast<float4*>(out)[(b << 8) + c4] = v;
}

// ---------------------------------------------------------------------------
extern "C" void kernel_launch(void* const* d_in, const int* in_sizes, int n_in,
                              void* d_out, int out_size) {
    const float* activated      = (const float*)d_in[0];
    const int*   expert_indices = (const int*)  d_in[1];
    const float* expert_weights = (const float*)d_in[2];
    const float* mlp2_weight    = (const float*)d_in[3];
    const float* mlp2_bias      = (const float*)d_in[4];
    const float* residual_x     = (const float*)d_in[5];
    float*       out            = (float*)d_out;

    static bool attr_done = false;
    if (!attr_done) {
        cudaFuncSetAttribute(matvec, cudaFuncAttributeMaxDynamicSharedMemorySize,
                             DYN_BYTES);
        attr_done = true;
    }

    dim3 grid(2, CC / MT, EE);   // ~136 active CTAs, one wave
    matvec<<<grid, THREADS, DYN_BYTES>>>(activated, mlp2_weight, expert_indices);

    finalize<<<(BB * CC / 4) / 128, 128>>>(residual_x, mlp2_bias,
                                           expert_weights, expert_indices, out);
}